// round 7
// baseline (speedup 1.0000x reference)
#include <cuda_runtime.h>

#define N_NODES 200000
#define C_DIM 256
#define H_DIM 64
#define K_DIM 3
#define G_DIM 512

// ---------------- scratch (device globals; no allocation allowed) ----------
__device__ float    g_scores[N_NODES * K_DIM];
__device__ unsigned g_menc[G_DIM * K_DIM];
__device__ float    g_denom[G_DIM * K_DIM];
__device__ int      g_argmin[G_DIM * K_DIM];

// ---------------- helpers --------------------------------------------------
__device__ __forceinline__ unsigned fenc(float f) {
    unsigned u = __float_as_uint(f);
    return u ^ ((u >> 31) ? 0xFFFFFFFFu : 0x80000000u);
}
__device__ __forceinline__ float fdec(unsigned e) {
    unsigned u = (e & 0x80000000u) ? (e ^ 0x80000000u) : ~e;
    return __uint_as_float(u);
}
__device__ __forceinline__ float lrelu(float v) { return v > 0.f ? v : 0.01f * v; }
__device__ __forceinline__ int clampg(int g) { return min(max(g, 0), G_DIM - 1); }

// ---------------- K0: init reduction buffers -------------------------------
__global__ void k_init() {
    int i = blockIdx.x * blockDim.x + threadIdx.x;
    if (i < G_DIM * K_DIM) {
        g_menc[i]   = 0u;        // encodes below every finite float
        g_denom[i]  = 0.f;
        g_argmin[i] = N_NODES;
    }
}

// ---------------- K1: scores + segment max (plain atomics) -----------------
#define SC_ROWS 128
#define SC_CHUNK 32
#define XS_PAD 132   // 132 % 32 == 4 -> conflict-free compute reads

__global__ __launch_bounds__(SC_ROWS) void k_scores(
    const float* __restrict__ x, const int* __restrict__ batch,
    const float* __restrict__ W1, const float* __restrict__ b1,
    const float* __restrict__ W2, const float* __restrict__ b2)
{
    __shared__ __align__(16) float W1s[SC_CHUNK * H_DIM];
    __shared__ __align__(16) float xs[SC_CHUNK * XS_PAD];
    __shared__ float W2s[H_DIM * K_DIM];
    __shared__ float b1s[H_DIM];
    __shared__ float b2s[K_DIM];

    const int t  = threadIdx.x;
    const int r0 = blockIdx.x * SC_ROWS;
    const int n  = r0 + t;
    const bool valid = n < N_NODES;
    const int rows = min(SC_ROWS, N_NODES - r0);

    // FIX: W2 has 192 elements but block has 128 threads -> strided load
    for (int i = t; i < H_DIM * K_DIM; i += SC_ROWS) W2s[i] = W2[i];
    if (t < H_DIM) b1s[t] = b1[t];
    if (t < K_DIM) b2s[t] = b2[t];

    float acc[H_DIM];
#pragma unroll
    for (int i = 0; i < H_DIM; i++) acc[i] = 0.f;

    for (int c0 = 0; c0 < C_DIM; c0 += SC_CHUNK) {
        __syncthreads();
        {
            const float4* src = (const float4*)(W1 + c0 * H_DIM);
            float4* dst = (float4*)W1s;
            for (int i = t; i < SC_CHUNK * H_DIM / 4; i += SC_ROWS) dst[i] = src[i];
        }
        for (int f = t; f < SC_ROWS * (SC_CHUNK / 4); f += SC_ROWS) {
            int row = f >> 3, c4 = f & 7;
            if (row < rows) {
                float4 v = *(const float4*)(x + (size_t)(r0 + row) * C_DIM + c0 + 4 * c4);
                xs[(4 * c4 + 0) * XS_PAD + row] = v.x;
                xs[(4 * c4 + 1) * XS_PAD + row] = v.y;
                xs[(4 * c4 + 2) * XS_PAD + row] = v.z;
                xs[(4 * c4 + 3) * XS_PAD + row] = v.w;
            }
        }
        __syncthreads();
#pragma unroll 2
        for (int j = 0; j < SC_CHUNK; j++) {
            float xv = xs[j * XS_PAD + t];
            const float4* wp = (const float4*)(W1s + j * H_DIM);
#pragma unroll
            for (int q = 0; q < H_DIM / 4; q++) {
                float4 w = wp[q];
                acc[4 * q + 0] = fmaf(xv, w.x, acc[4 * q + 0]);
                acc[4 * q + 1] = fmaf(xv, w.y, acc[4 * q + 1]);
                acc[4 * q + 2] = fmaf(xv, w.z, acc[4 * q + 2]);
                acc[4 * q + 3] = fmaf(xv, w.w, acc[4 * q + 3]);
            }
        }
    }

    float sc[K_DIM];
#pragma unroll
    for (int k = 0; k < K_DIM; k++) sc[k] = b2s[k];
#pragma unroll
    for (int h = 0; h < H_DIM; h++) {
        float hv = lrelu(acc[h] + b1s[h]);
#pragma unroll
        for (int k = 0; k < K_DIM; k++)
            sc[k] = fmaf(hv, W2s[h * K_DIM + k], sc[k]);
    }

    if (valid) {
        int g = clampg(batch[n]);
#pragma unroll
        for (int k = 0; k < K_DIM; k++) {
            g_scores[(size_t)n * K_DIM + k] = sc[k];
            atomicMax(&g_menc[g * K_DIM + k], fenc(sc[k]));
        }
    }
}

// ---------------- K2: exp-sum (denom) + argmin of argmax -------------------
__global__ void k_reduce(const int* __restrict__ batch) {
    int n = blockIdx.x * blockDim.x + threadIdx.x;
    if (n >= N_NODES) return;
    int g = clampg(batch[n]);
#pragma unroll
    for (int k = 0; k < K_DIM; k++) {
        float s = g_scores[(size_t)n * K_DIM + k];
        float m = fdec(g_menc[g * K_DIM + k]);
        float e = expf(s - m);
        atomicAdd(&g_denom[g * K_DIM + k], e);
        if (s == m) atomicMin(&g_argmin[g * K_DIM + k], n);
    }
}

// ---------------- K3: gather + feat@Wh + lrelu -----------------------------
#define GPB 8
__global__ __launch_bounds__(C_DIM) void k_final(
    const float* __restrict__ x, const int* __restrict__ batch,
    const float* __restrict__ Wh, const float* __restrict__ bh,
    float* __restrict__ out)
{
    __shared__ float feat[GPB][K_DIM * C_DIM];
    __shared__ float sg_s[GPB][K_DIM];
    __shared__ int   idx_s[GPB][K_DIM];

    const int t  = threadIdx.x;
    const int g0 = blockIdx.x * GPB;

    if (t < GPB * K_DIM) {
        int gi = t / K_DIM, k = t % K_DIM;
        int g = g0 + gi;
        int idx = min(g_argmin[g * K_DIM + k], N_NODES - 1);
        int gb = clampg(batch[idx]);
        float m = fdec(g_menc[gb * K_DIM + k]);
        float sg = expf(g_scores[(size_t)idx * K_DIM + k] - m) / g_denom[gb * K_DIM + k];
        sg_s[gi][k] = sg;
        idx_s[gi][k] = idx;
    }
    __syncthreads();

#pragma unroll
    for (int seg = 0; seg < GPB * K_DIM; seg++) {
        int gi = seg / K_DIM, k = seg % K_DIM;
        feat[gi][k * C_DIM + t] = x[(size_t)idx_s[gi][k] * C_DIM + t] * sg_s[gi][k];
    }
    __syncthreads();

    float acc[GPB];
    float bhv = __ldg(&bh[t]);
#pragma unroll
    for (int gi = 0; gi < GPB; gi++) acc[gi] = bhv;

#pragma unroll 4
    for (int r = 0; r < K_DIM * C_DIM; r++) {
        float wv = __ldg(&Wh[(size_t)r * C_DIM + t]);
#pragma unroll
        for (int gi = 0; gi < GPB; gi++) acc[gi] = fmaf(feat[gi][r], wv, acc[gi]);
    }
#pragma unroll
    for (int gi = 0; gi < GPB; gi++)
        out[(size_t)(g0 + gi) * C_DIM + t] = lrelu(acc[gi]);
}

// ---------------- launch: bind inputs by UNIQUE element count ---------------
extern "C" void kernel_launch(void* const* d_in, const int* in_sizes, int n_in,
                              void* d_out, int out_size) {
    // roles: 0=x 1=batch 2=W1 3=b1 4=W2 5=b2 6=Wh 7=bh
    const int want[8] = {51200000, 200000, 16384, 64, 192, 3, 196608, 256};
    const void* p[8];
    for (int r = 0; r < 8; r++) p[r] = (r < n_in) ? d_in[r] : nullptr;  // positional default
    for (int r = 0; r < 8; r++)
        for (int i = 0; i < n_in; i++)
            if (in_sizes[i] == want[r]) { p[r] = d_in[i]; break; }

    const float* x     = (const float*)p[0];
    const int*   batch = (const int*)p[1];
    const float* W1    = (const float*)p[2];
    const float* b1    = (const float*)p[3];
    const float* W2    = (const float*)p[4];
    const float* b2    = (const float*)p[5];
    const float* Wh    = (const float*)p[6];
    const float* bh    = (const float*)p[7];
    float* out = (float*)d_out;

    k_init<<<(G_DIM * K_DIM + 255) / 256, 256>>>();
    k_scores<<<(N_NODES + SC_ROWS - 1) / SC_ROWS, SC_ROWS>>>(x, batch, W1, b1, W2, b2);
    k_reduce<<<(N_NODES + 255) / 256, 256>>>(batch);
    k_final<<<G_DIM / GPB, C_DIM>>>(x, batch, Wh, bh, out);
}

// round 8
// speedup vs baseline: 1.4750x; 1.4750x over previous
#include <cuda_runtime.h>

#define N_NODES 200000
#define C_DIM 256
#define H_DIM 64
#define K_DIM 3
#define G_DIM 512

// ---------------- scratch (device globals; no allocation allowed) ----------
__device__ float    g_scores[N_NODES * K_DIM];
__device__ unsigned g_menc[G_DIM * K_DIM];
__device__ float    g_denom[G_DIM * K_DIM];
__device__ int      g_argmin[G_DIM * K_DIM];

// ---------------- helpers --------------------------------------------------
__device__ __forceinline__ unsigned fenc(float f) {
    unsigned u = __float_as_uint(f);
    return u ^ ((u >> 31) ? 0xFFFFFFFFu : 0x80000000u);
}
__device__ __forceinline__ float fdec(unsigned e) {
    unsigned u = (e & 0x80000000u) ? (e ^ 0x80000000u) : ~e;
    return __uint_as_float(u);
}
__device__ __forceinline__ float lrelu(float v) { return v > 0.f ? v : 0.01f * v; }
__device__ __forceinline__ int clampg(int g) { return min(max(g, 0), G_DIM - 1); }

// packed f32x2 helpers (PTX-only path; ptxas won't auto-fuse FFMA2)
__device__ __forceinline__ void fma2(unsigned long long& acc,
                                     unsigned long long a, unsigned long long b) {
    asm("fma.rn.f32x2 %0, %1, %2, %0;" : "+l"(acc) : "l"(a), "l"(b));
}
__device__ __forceinline__ unsigned long long dup2(float v) {
    unsigned long long r;
    unsigned u = __float_as_uint(v);
    asm("mov.b64 %0, {%1, %1};" : "=l"(r) : "r"(u));
    return r;
}
__device__ __forceinline__ void unpk2(unsigned long long v, float& lo, float& hi) {
    unsigned a, b;
    asm("mov.b64 {%0, %1}, %2;" : "=r"(a), "=r"(b) : "l"(v));
    lo = __uint_as_float(a); hi = __uint_as_float(b);
}

// ---------------- K0: init reduction buffers -------------------------------
__global__ void k_init() {
    int i = blockIdx.x * blockDim.x + threadIdx.x;
    if (i < G_DIM * K_DIM) {
        g_menc[i]   = 0u;        // encodes below every finite float
        g_denom[i]  = 0.f;
        g_argmin[i] = N_NODES;
    }
}

// ---------------- K1: scores (8x8 register tile, FFMA2) --------------------
#define SC_ROWS 128      // rows (nodes) per block
#define SC_CHUNK 32      // k-depth per stage
#define XS_PAD 132       // floats; 16B-aligned stride, bank-spread
#define W1_PAD 68        // floats; 16B-aligned stride

__global__ __launch_bounds__(SC_ROWS) void k_scores(
    const float* __restrict__ x, const int* __restrict__ batch,
    const float* __restrict__ W1, const float* __restrict__ b1,
    const float* __restrict__ W2, const float* __restrict__ b2)
{
    __shared__ __align__(16) float W1s[SC_CHUNK][W1_PAD];   // 8.5 KB
    __shared__ __align__(16) float xs[SC_CHUNK][XS_PAD];    // 16.5 KB
    __shared__ float W2s[H_DIM * K_DIM];
    __shared__ float b1s[H_DIM];
    __shared__ float b2s[K_DIM];

    const int t  = threadIdx.x;
    const int r0 = blockIdx.x * SC_ROWS;
    const int rows = min(SC_ROWS, N_NODES - r0);
    const int rb = (t >> 3) * 8;    // tile-local row base (8 rows, 4 f32x2 pairs)
    const int cb = (t & 7) * 8;     // h column base (8 cols)

    for (int i = t; i < H_DIM * K_DIM; i += SC_ROWS) W2s[i] = W2[i];
    if (t < H_DIM) b1s[t] = b1[t];
    if (t < K_DIM) b2s[t] = b2[t];

    unsigned long long acc[4][8];
#pragma unroll
    for (int p = 0; p < 4; p++)
#pragma unroll
        for (int q = 0; q < 8; q++) acc[p][q] = 0ull;

    for (int c0 = 0; c0 < C_DIM; c0 += SC_CHUNK) {
        __syncthreads();
        // stage W1 chunk [32 k][64 h] (coalesced float4)
        for (int i = t; i < SC_CHUNK * (H_DIM / 4); i += SC_ROWS) {
            int k = i >> 4, h4 = i & 15;
            *(float4*)&W1s[k][h4 * 4] =
                ((const float4*)(W1 + (size_t)(c0 + k) * H_DIM))[h4];
        }
        // stage x tile [128 rows][32 k] -> xs[k][row] (coalesced float4 reads)
        for (int f = t; f < SC_ROWS * (SC_CHUNK / 4); f += SC_ROWS) {
            int row = f >> 3, c4 = f & 7;
            if (row < rows) {
                float4 v = *(const float4*)(x + (size_t)(r0 + row) * C_DIM + c0 + 4 * c4);
                xs[4 * c4 + 0][row] = v.x;
                xs[4 * c4 + 1][row] = v.y;
                xs[4 * c4 + 2][row] = v.z;
                xs[4 * c4 + 3][row] = v.w;
            }
        }
        __syncthreads();
#pragma unroll 2
        for (int j = 0; j < SC_CHUNK; j++) {
            // 8 rows as 4 packed pairs (16B shared loads, natural f32x2 packing)
            const ulonglong2* xp = (const ulonglong2*)&xs[j][rb];
            ulonglong2 xa = xp[0], xb = xp[1];
            unsigned long long xr[4] = {xa.x, xa.y, xb.x, xb.y};
            // 8 W1 scalars, duplicated into f32x2
            float4 wa = *(const float4*)&W1s[j][cb];
            float4 wb = *(const float4*)&W1s[j][cb + 4];
            unsigned long long wd[8] = {
                dup2(wa.x), dup2(wa.y), dup2(wa.z), dup2(wa.w),
                dup2(wb.x), dup2(wb.y), dup2(wb.z), dup2(wb.w)};
#pragma unroll
            for (int p = 0; p < 4; p++)
#pragma unroll
                for (int q = 0; q < 8; q++)
                    fma2(acc[p][q], xr[p], wd[q]);
        }
    }

    // epilogue: bias + lrelu + @W2 partials, then 8-lane butterfly reduce
    float scp[8][K_DIM];
#pragma unroll
    for (int i = 0; i < 8; i++)
#pragma unroll
        for (int k = 0; k < K_DIM; k++) scp[i][k] = 0.f;

#pragma unroll
    for (int p = 0; p < 4; p++)
#pragma unroll
        for (int q = 0; q < 8; q++) {
            float lo, hi; unpk2(acc[p][q], lo, hi);
            int h = cb + q;
            float hv0 = lrelu(lo + b1s[h]);
            float hv1 = lrelu(hi + b1s[h]);
#pragma unroll
            for (int k = 0; k < K_DIM; k++) {
                float w = W2s[h * K_DIM + k];
                scp[2 * p + 0][k] = fmaf(hv0, w, scp[2 * p + 0][k]);
                scp[2 * p + 1][k] = fmaf(hv1, w, scp[2 * p + 1][k]);
            }
        }

    const unsigned FULL = 0xFFFFFFFFu;
#pragma unroll
    for (int o = 1; o < 8; o <<= 1)
#pragma unroll
        for (int i = 0; i < 8; i++)
#pragma unroll
            for (int k = 0; k < K_DIM; k++)
                scp[i][k] += __shfl_xor_sync(FULL, scp[i][k], o);

    // lane (t&7) takes row (t&7) of this rowgroup
    int lr = t & 7;
    int n = r0 + rb + lr;
    if (n < N_NODES) {
        int g = clampg(batch[n]);
#pragma unroll
        for (int k = 0; k < K_DIM; k++) {
            float s = scp[lr][k] + b2s[k];
            g_scores[(size_t)n * K_DIM + k] = s;
            atomicMax(&g_menc[g * K_DIM + k], fenc(s));
        }
    }
}

// ---------------- K2: exp-sum (denom) + argmin of argmax -------------------
__global__ void k_reduce(const int* __restrict__ batch) {
    int n = blockIdx.x * blockDim.x + threadIdx.x;
    if (n >= N_NODES) return;
    int g = clampg(batch[n]);
#pragma unroll
    for (int k = 0; k < K_DIM; k++) {
        float s = g_scores[(size_t)n * K_DIM + k];
        float m = fdec(g_menc[g * K_DIM + k]);
        float e = expf(s - m);
        atomicAdd(&g_denom[g * K_DIM + k], e);
        if (s == m) atomicMin(&g_argmin[g * K_DIM + k], n);
    }
}

// ---------------- K3: gather + feat@Wh + lrelu (1024 thr, 4-way r split) ---
#define GPB 8
#define KF_THREADS 1024
__global__ __launch_bounds__(KF_THREADS) void k_final(
    const float* __restrict__ x, const int* __restrict__ batch,
    const float* __restrict__ Wh, const float* __restrict__ bh,
    float* __restrict__ out)
{
    __shared__ float feat[GPB][K_DIM * C_DIM];   // 24 KB; reused as reduce buf
    __shared__ float sg_s[GPB][K_DIM];
    __shared__ int   idx_s[GPB][K_DIM];

    const int t  = threadIdx.x;
    const int g0 = blockIdx.x * GPB;

    if (t < GPB * K_DIM) {
        int gi = t / K_DIM, k = t % K_DIM;
        int g = g0 + gi;
        int idx = min(g_argmin[g * K_DIM + k], N_NODES - 1);
        int gb = clampg(batch[idx]);
        float m = fdec(g_menc[gb * K_DIM + k]);
        float sg = expf(g_scores[(size_t)idx * K_DIM + k] - m) / g_denom[gb * K_DIM + k];
        sg_s[gi][k] = sg;
        idx_s[gi][k] = idx;
    }
    __syncthreads();

    for (int idx = t; idx < GPB * K_DIM * C_DIM; idx += KF_THREADS) {
        int gi = idx / (K_DIM * C_DIM);
        int rem = idx - gi * (K_DIM * C_DIM);
        int k = rem >> 8, c = rem & 255;
        feat[gi][rem] = x[(size_t)idx_s[gi][k] * C_DIM + c] * sg_s[gi][k];
    }
    __syncthreads();

    const int col = t & 255;        // output column
    const int rs  = t >> 8;         // r-segment 0..3 (192 r each)
    float acc[GPB];
#pragma unroll
    for (int gi = 0; gi < GPB; gi++) acc[gi] = 0.f;

    const int rbeg = rs * 192, rend = rbeg + 192;
#pragma unroll 4
    for (int r = rbeg; r < rend; r++) {
        float wv = __ldg(&Wh[(size_t)r * C_DIM + col]);
#pragma unroll
        for (int gi = 0; gi < GPB; gi++) acc[gi] = fmaf(feat[gi][r], wv, acc[gi]);
    }

    __syncthreads();   // feat reads done; safe to reuse as reduce buffer
    float* red = &feat[0][0];       // alias: [3][GPB][256] = 6144 floats
    if (rs > 0) {
#pragma unroll
        for (int gi = 0; gi < GPB; gi++)
            red[((rs - 1) * GPB + gi) * C_DIM + col] = acc[gi];
    }
    __syncthreads();
    if (rs == 0) {
        float bhv = __ldg(&bh[col]);
#pragma unroll
        for (int gi = 0; gi < GPB; gi++) {
            float v = acc[gi]
                    + red[(0 * GPB + gi) * C_DIM + col]
                    + red[(1 * GPB + gi) * C_DIM + col]
                    + red[(2 * GPB + gi) * C_DIM + col]
                    + bhv;
            out[(size_t)(g0 + gi) * C_DIM + col] = lrelu(v);
        }
    }
}

// ---------------- launch: bind inputs by UNIQUE element count ---------------
extern "C" void kernel_launch(void* const* d_in, const int* in_sizes, int n_in,
                              void* d_out, int out_size) {
    // roles: 0=x 1=batch 2=W1 3=b1 4=W2 5=b2 6=Wh 7=bh
    const int want[8] = {51200000, 200000, 16384, 64, 192, 3, 196608, 256};
    const void* p[8];
    for (int r = 0; r < 8; r++) p[r] = (r < n_in) ? d_in[r] : nullptr;
    for (int r = 0; r < 8; r++)
        for (int i = 0; i < n_in; i++)
            if (in_sizes[i] == want[r]) { p[r] = d_in[i]; break; }

    const float* x     = (const float*)p[0];
    const int*   batch = (const int*)p[1];
    const float* W1    = (const float*)p[2];
    const float* b1    = (const float*)p[3];
    const float* W2    = (const float*)p[4];
    const float* b2    = (const float*)p[5];
    const float* Wh    = (const float*)p[6];
    const float* bh    = (const float*)p[7];
    float* out = (float*)d_out;

    k_init<<<(G_DIM * K_DIM + 255) / 256, 256>>>();
    k_scores<<<(N_NODES + SC_ROWS - 1) / SC_ROWS, SC_ROWS>>>(x, batch, W1, b1, W2, b2);
    k_reduce<<<(N_NODES + 255) / 256, 256>>>(batch);
    k_final<<<G_DIM / GPB, KF_THREADS>>>(x, batch, Wh, bh, out);
}